// round 1
// baseline (speedup 1.0000x reference)
#include <cuda_runtime.h>
#include <cstdint>

// ---------------------------------------------------------------------------
// Problem constants
// ---------------------------------------------------------------------------
#define BATCH   512
#define MAXLEN  128
#define D_DRUG  256
#define D_CELL  1024
#define NHEAD   16
#define HDIM    64
#define EMB     1024   // NHEAD*HDIM

// ---------------------------------------------------------------------------
// Scratch (device globals: allocation-free, sanctioned by harness rules)
// ---------------------------------------------------------------------------
__device__ float g_cq [BATCH * EMB];            // cell query fc out
__device__ float g_q  [BATCH * EMB];            // scaled q
__device__ float g_qk [BATCH * NHEAD * D_DRUG]; // q folded through Wk (per head)
__device__ float g_xa [BATCH * NHEAD * D_DRUG]; // attn-weighted x sums
__device__ float g_op [BATCH * EMB];            // pre-Wo output
__device__ int   g_seg[BATCH + 1];              // segment starts

// ---------------------------------------------------------------------------
// Packed f32x2 FMA helpers (sm_103a: doubles FFMA throughput vs scalar)
// ---------------------------------------------------------------------------
union F2U { float2 f; unsigned long long u; };

__device__ __forceinline__ void fma2(F2U &c, F2U a, F2U b) {
    asm("fma.rn.f32x2 %0, %1, %2, %0;" : "+l"(c.u) : "l"(a.u), "l"(b.u));
}

// ---------------------------------------------------------------------------
// Segment starts: lower_bound binary search per graph id.
// Handles guide stored as int32 OR int64 (auto-detect from top bytes).
// ---------------------------------------------------------------------------
__global__ void seg_kernel(const void* __restrict__ guide, int n, int* __restrict__ seg)
{
    int g = blockIdx.x * blockDim.x + threadIdx.x;
    if (g > BATCH) return;
    const unsigned long long* g64 = (const unsigned long long*)guide;
    const int*                g32 = (const int*)guide;
    // int64 data: last u64 element is a graph id <= 511.
    // int32 data: that u64 aliases (guide[n-1]<<32)|guide[n-2] -> huge (unless all zero,
    // in which case both interpretations give identical segmentation).
    bool is64 = (g64[(n >> 1) - 1] <= 511ull);
    int lo = 0, hi = n;
    while (lo < hi) {
        int mid = (lo + hi) >> 1;
        long long v = is64 ? (long long)g64[mid] : (long long)g32[mid];
        if (v < (long long)g) lo = mid + 1; else hi = mid;
    }
    seg[g] = lo;
}

// ---------------------------------------------------------------------------
// Copy cell -> out[:, EMB : EMB+D_CELL]
// ---------------------------------------------------------------------------
__global__ void copy_cell_kernel(const float4* __restrict__ cell, float4* __restrict__ out)
{
    int i = blockIdx.x * blockDim.x + threadIdx.x;   // BATCH * (D_CELL/4) = 131072
    if (i >= BATCH * (D_CELL / 4)) return;
    int b = i >> 8, j = i & 255;                     // 256 float4 per row
    out[b * ((EMB + D_CELL) / 4) + (EMB / 4) + j] = cell[i];
}

// ---------------------------------------------------------------------------
// SGEMM: C = alpha * (A x op(W) + bias_row)
//   TRANS_W = true : W is [N,K] row-major (both operands K-contiguous, "NT")
//   TRANS_W = false: W is [K,N] row-major ("NN")
// Tile 64x64x16, 256 threads, 4x4 microtile, f32x2 accumulation,
// double-buffered smem with register prefetch.
// Requires M%64==0, N%64==0, K%16==0 (all call sites satisfy this).
// blockIdx.z = batch slice (head), with explicit z-strides.
// ---------------------------------------------------------------------------
#define BM 64
#define BN 64
#define BKK 16
#define SPAD 68

template <bool TRANS_W>
__global__ __launch_bounds__(256)
void sgemm_kernel(int M, int N, int K,
                  const float* __restrict__ A, int lda, long long sAz,
                  const float* __restrict__ W, int ldw, long long sWz,
                  const float* __restrict__ bias, long long sbz,
                  float* __restrict__ C, int ldc, long long sCz,
                  float alpha)
{
    __shared__ float As[2][BKK * SPAD];
    __shared__ float Ws[2][BKK * SPAD];

    int z = blockIdx.z;
    A += (long long)z * sAz;
    W += (long long)z * sWz;
    C += (long long)z * sCz;
    const float* biasp = bias ? bias + (long long)z * sbz : nullptr;

    int m0 = blockIdx.y * BM;
    int n0 = blockIdx.x * BN;
    int tid = threadIdx.x;

    // load-thread mapping (K-contiguous operands): 64 rows x 4 k-quads
    int arow = tid >> 2;
    int akq  = (tid & 3) * 4;
    // NN B tile mapping: 16 k-rows x 16 n-quads
    int bkr  = tid >> 4;
    int bnq  = (tid & 15) * 4;

    const float* Aptr = A + (long long)(m0 + arow) * lda + akq;
    const float* Wptr = TRANS_W ? (W + (long long)(n0 + arow) * ldw + akq)
                                : (W + (long long)bkr * ldw + n0 + bnq);

    // compute-thread mapping
    int tm = (tid >> 4) * 4;
    int tn = (tid & 15) * 4;

    F2U acc[4][2];
#pragma unroll
    for (int i = 0; i < 4; i++) { acc[i][0].f = make_float2(0.f, 0.f); acc[i][1].f = make_float2(0.f, 0.f); }

    // prologue: tile 0
    float4 ra = *(const float4*)Aptr;
    float4 rw = *(const float4*)Wptr;
    {
        As[0][(akq + 0) * SPAD + arow] = ra.x;
        As[0][(akq + 1) * SPAD + arow] = ra.y;
        As[0][(akq + 2) * SPAD + arow] = ra.z;
        As[0][(akq + 3) * SPAD + arow] = ra.w;
        if (TRANS_W) {
            Ws[0][(akq + 0) * SPAD + arow] = rw.x;
            Ws[0][(akq + 1) * SPAD + arow] = rw.y;
            Ws[0][(akq + 2) * SPAD + arow] = rw.z;
            Ws[0][(akq + 3) * SPAD + arow] = rw.w;
        } else {
            *(float4*)&Ws[0][bkr * SPAD + bnq] = rw;
        }
    }
    __syncthreads();

    int KT = K / BKK;
    int buf = 0;
    for (int kt = 0; kt < KT; kt++) {
        if (kt + 1 < KT) {
            ra = *(const float4*)(Aptr + (long long)(kt + 1) * BKK);
            rw = TRANS_W ? *(const float4*)(Wptr + (long long)(kt + 1) * BKK)
                         : *(const float4*)(Wptr + (long long)(kt + 1) * BKK * ldw);
        }

        const float* pa = &As[buf][0];
        const float* pw = &Ws[buf][0];
#pragma unroll
        for (int kk = 0; kk < BKK; kk++) {
            float4 av = *(const float4*)(pa + kk * SPAD + tm);
            float4 bv = *(const float4*)(pw + kk * SPAD + tn);
            F2U b0, b1, a;
            b0.f = make_float2(bv.x, bv.y);
            b1.f = make_float2(bv.z, bv.w);
            a.f = make_float2(av.x, av.x); fma2(acc[0][0], a, b0); fma2(acc[0][1], a, b1);
            a.f = make_float2(av.y, av.y); fma2(acc[1][0], a, b0); fma2(acc[1][1], a, b1);
            a.f = make_float2(av.z, av.z); fma2(acc[2][0], a, b0); fma2(acc[2][1], a, b1);
            a.f = make_float2(av.w, av.w); fma2(acc[3][0], a, b0); fma2(acc[3][1], a, b1);
        }

        if (kt + 1 < KT) {
            int nb = buf ^ 1;
            As[nb][(akq + 0) * SPAD + arow] = ra.x;
            As[nb][(akq + 1) * SPAD + arow] = ra.y;
            As[nb][(akq + 2) * SPAD + arow] = ra.z;
            As[nb][(akq + 3) * SPAD + arow] = ra.w;
            if (TRANS_W) {
                Ws[nb][(akq + 0) * SPAD + arow] = rw.x;
                Ws[nb][(akq + 1) * SPAD + arow] = rw.y;
                Ws[nb][(akq + 2) * SPAD + arow] = rw.z;
                Ws[nb][(akq + 3) * SPAD + arow] = rw.w;
            } else {
                *(float4*)&Ws[nb][bkr * SPAD + bnq] = rw;
            }
        }
        __syncthreads();
        buf ^= 1;
    }

    float b4[4] = {0.f, 0.f, 0.f, 0.f};
    if (biasp) {
        b4[0] = biasp[n0 + tn + 0];
        b4[1] = biasp[n0 + tn + 1];
        b4[2] = biasp[n0 + tn + 2];
        b4[3] = biasp[n0 + tn + 3];
    }
#pragma unroll
    for (int i = 0; i < 4; i++) {
        float4 o;
        o.x = alpha * (acc[i][0].f.x + b4[0]);
        o.y = alpha * (acc[i][0].f.y + b4[1]);
        o.z = alpha * (acc[i][1].f.x + b4[2]);
        o.w = alpha * (acc[i][1].f.y + b4[3]);
        *(float4*)(C + (long long)(m0 + tm + i) * ldc + n0 + tn) = o;
    }
}

// ---------------------------------------------------------------------------
// Fused attention: per-graph scores -> softmax -> attn-weighted x sums.
//   scores[h,m] = qk[b,h,:] . x[s0+m,:]          (16 x len, len<=128)
//   xa[b,h,:]   = sum_m attn[h,m] * x[s0+m,:]    (16 x 256)
// One block per graph, 256 threads.
// ---------------------------------------------------------------------------
__global__ __launch_bounds__(256)
void attn_kernel(const float* __restrict__ x,
                 const float* __restrict__ qk,
                 const int*   __restrict__ seg,
                 float*       __restrict__ xa)
{
    __shared__ float qks[16 * 260];
    __shared__ float xs [16 * 260];
    __shared__ float sc [16 * 132];

    int b = blockIdx.x;
    int t = threadIdx.x;
    int s0 = seg[b];
    int len = seg[b + 1] - s0;
    if (len > MAXLEN) len = MAXLEN;   // reference drops pos>=128 (OOB scatter)

    // stage qk[b] (16 x 256)
    const float4* qk4 = (const float4*)(qk + (long long)b * (NHEAD * D_DRUG));
#pragma unroll
    for (int r = 0; r < 4; r++) {
        int idx = t + r * 256;
        int h = idx >> 6, jj = idx & 63;
        *(float4*)&qks[h * 260 + jj * 4] = qk4[idx];
    }
    __syncthreads();

    // ---- scores: chunks of 16 nodes, thread = (head, node-in-chunk) ----
    int hh = t >> 4, mm = t & 15;
    for (int m0 = 0; m0 < len; m0 += 16) {
        int nm = len - m0; if (nm > 16) nm = 16;
#pragma unroll
        for (int r = 0; r < 4; r++) {
            int idx = t + r * 256;
            int row = idx >> 6, jj = idx & 63;
            if (row < nm)
                *(float4*)&xs[row * 260 + jj * 4] =
                    *(const float4*)(x + (long long)(s0 + m0 + row) * D_DRUG + jj * 4);
        }
        __syncthreads();
        if (mm < nm) {
            const float* qp = &qks[hh * 260];
            const float* xp = &xs[mm * 260];
            F2U acc0, acc1;
            acc0.f = make_float2(0.f, 0.f);
            acc1.f = make_float2(0.f, 0.f);
#pragma unroll
            for (int j = 0; j < 256; j += 8) {
                float4 a0 = *(const float4*)(qp + j);
                float4 b0 = *(const float4*)(xp + j);
                float4 a1 = *(const float4*)(qp + j + 4);
                float4 b1 = *(const float4*)(xp + j + 4);
                F2U aa, bb;
                aa.f = make_float2(a0.x, a0.y); bb.f = make_float2(b0.x, b0.y); fma2(acc0, aa, bb);
                aa.f = make_float2(a0.z, a0.w); bb.f = make_float2(b0.z, b0.w); fma2(acc1, aa, bb);
                aa.f = make_float2(a1.x, a1.y); bb.f = make_float2(b1.x, b1.y); fma2(acc0, aa, bb);
                aa.f = make_float2(a1.z, a1.w); bb.f = make_float2(b1.z, b1.w); fma2(acc1, aa, bb);
            }
            sc[hh * 132 + m0 + mm] = acc0.f.x + acc0.f.y + acc1.f.x + acc1.f.y;
        }
        __syncthreads();
    }

    // ---- softmax: warp w owns heads 2w, 2w+1 ----
    int w = t >> 5, lane = t & 31;
#pragma unroll
    for (int hq = 0; hq < 2; hq++) {
        int h = w * 2 + hq;
        float mx = -3.0e38f;
        for (int m = lane; m < len; m += 32) mx = fmaxf(mx, sc[h * 132 + m]);
#pragma unroll
        for (int o = 16; o; o >>= 1) mx = fmaxf(mx, __shfl_xor_sync(0xffffffffu, mx, o));
        float sum = 0.f;
        for (int m = lane; m < len; m += 32) {
            float e = __expf(sc[h * 132 + m] - mx);
            sc[h * 132 + m] = e;
            sum += e;
        }
#pragma unroll
        for (int o = 16; o; o >>= 1) sum += __shfl_xor_sync(0xffffffffu, sum, o);
        float inv = 1.0f / sum;
        for (int m = lane; m < len; m += 32) sc[h * 132 + m] *= inv;
    }
    __syncthreads();

    // ---- xa: thread = (head, 16-wide j chunk); rows are L1/L2-hot ----
    int h = t >> 4;
    int j0 = (t & 15) * 16;
    F2U acc[8];
#pragma unroll
    for (int i = 0; i < 8; i++) acc[i].f = make_float2(0.f, 0.f);
    for (int m = 0; m < len; m++) {
        float a = sc[h * 132 + m];
        F2U ad; ad.f = make_float2(a, a);
        const float4* xr = (const float4*)(x + (long long)(s0 + m) * D_DRUG + j0);
#pragma unroll
        for (int r = 0; r < 4; r++) {
            float4 v = xr[r];
            F2U b0, b1;
            b0.f = make_float2(v.x, v.y);
            b1.f = make_float2(v.z, v.w);
            fma2(acc[2 * r], ad, b0);
            fma2(acc[2 * r + 1], ad, b1);
        }
    }
    float* xo = xa + (long long)b * (NHEAD * D_DRUG) + h * D_DRUG + j0;
#pragma unroll
    for (int r = 0; r < 4; r++) {
        float4 o = make_float4(acc[2 * r].f.x, acc[2 * r].f.y,
                               acc[2 * r + 1].f.x, acc[2 * r + 1].f.y);
        *(float4*)(xo + r * 4) = o;
    }
}

// ---------------------------------------------------------------------------
// Launch
// ---------------------------------------------------------------------------
extern "C" void kernel_launch(void* const* d_in, const int* in_sizes, int n_in,
                              void* d_out, int out_size)
{
    const float* x_nodes = (const float*)d_in[0];
    const float* cell    = (const float*)d_in[1];
    const float* Wq      = (const float*)d_in[2];
    const float* bq      = (const float*)d_in[3];
    const float* Wk      = (const float*)d_in[4];
    /* bk = d_in[5]: cancels exactly in softmax */
    const float* Wv      = (const float*)d_in[6];
    const float* bv      = (const float*)d_in[7];
    const float* Wo      = (const float*)d_in[8];
    const float* bo      = (const float*)d_in[9];
    const float* Wc      = (const float*)d_in[10];
    const float* bc      = (const float*)d_in[11];
    const void*  guide   = d_in[12];
    float*       out     = (float*)d_out;

    int N = in_sizes[12];   // node count (element count, dtype-independent)

    float *cq, *q, *qkp, *xap, *op;
    int* seg;
    cudaGetSymbolAddress((void**)&cq,  g_cq);
    cudaGetSymbolAddress((void**)&q,   g_q);
    cudaGetSymbolAddress((void**)&qkp, g_qk);
    cudaGetSymbolAddress((void**)&xap, g_xa);
    cudaGetSymbolAddress((void**)&op,  g_op);
    cudaGetSymbolAddress((void**)&seg, g_seg);

    // independent prep
    seg_kernel<<<3, 256>>>(guide, N, seg);
    copy_cell_kernel<<<512, 256>>>((const float4*)cell, (float4*)out);

    // cq = cell @ Wc^T + bc                      [512,1024]x[1024,1024]
    sgemm_kernel<true><<<dim3(16, 8, 1), 256>>>(512, 1024, 1024,
        cell, 1024, 0, Wc, 1024, 0, bc, 0, cq, 1024, 0, 1.0f);

    // q = (cq @ Wq^T + bq) * HD^-0.5             [512,1024]x[1024,1024]
    sgemm_kernel<true><<<dim3(16, 8, 1), 256>>>(512, 1024, 1024,
        cq, 1024, 0, Wq, 1024, 0, bq, 0, q, 1024, 0, 0.125f);

    // qk[b,h,:] = q[b,h,:] @ Wk_h                16 x ([512,64]x[64,256], NN)
    sgemm_kernel<false><<<dim3(4, 8, 16), 256>>>(512, 256, 64,
        q, 1024, 64, Wk, 256, 64 * 256, nullptr, 0, qkp, 4096, 256, 1.0f);

    // fused scores -> softmax -> xa (one block per graph)
    attn_kernel<<<512, 256>>>(x_nodes, qkp, seg, xap);

    // out_pre[b,h,:] = xa[b,h,:] @ Wv_h^T + bv_h 16 x ([512,256]x[256,64], NT)
    sgemm_kernel<true><<<dim3(1, 8, 16), 256>>>(512, 64, 256,
        xap, 4096, 256, Wv, 256, 64 * 256, bv, 64, op, 1024, 64, 1.0f);

    // out[:, :1024] = out_pre @ Wo^T + bo        [512,1024]x[1024,1024]
    sgemm_kernel<true><<<dim3(16, 8, 1), 256>>>(512, 1024, 1024,
        op, 1024, 0, Wo, 1024, 0, bo, 0, out, 2048, 0, 1.0f);

    (void)n_in; (void)out_size;
}